// round 4
// baseline (speedup 1.0000x reference)
#include <cuda_runtime.h>
#include <cstddef>

#define N_ROWS 4096
#define CH     256
#define NC     1000

// ---- scratch (static device globals; no runtime allocation) ----
__device__ float g_invn[N_ROWS];
__device__ float g_G[CH * CH];        // gram:  G = X^T D^-1 X (symmetric)
__device__ float g_s[NC * CH];        // per-class sum of invn_r * x_r
__device__ float g_t[NC * CH];        // per-class sum of x_r
__device__ float g_counts[NC];

// ---------------------------------------------------------------
// K1: prep — norms + zero accumulators
// ---------------------------------------------------------------
__global__ void k_prep(const float* __restrict__ x) {
    int b = blockIdx.x;
    int tid = threadIdx.x;
    if (b < 512) {
        int warp = ((b << 8) + tid) >> 5;       // 0..4095
        int lane = tid & 31;
        const float4* p = (const float4*)(x + (size_t)warp * CH);
        float ss = 0.0f;
#pragma unroll
        for (int k = lane; k < 64; k += 32) {
            float4 v = p[k];
            ss += v.x * v.x + v.y * v.y + v.z * v.z + v.w * v.w;
        }
#pragma unroll
        for (int off = 16; off; off >>= 1)
            ss += __shfl_xor_sync(0xffffffffu, ss, off);
        if (lane == 0) g_invn[warp] = rsqrtf(ss);
    } else if (b < 576) {
        ((float4*)g_G)[(b - 512) * 256 + tid] = make_float4(0.f, 0.f, 0.f, 0.f);
    } else if (b < 826) {
        ((float4*)g_s)[(b - 576) * 256 + tid] = make_float4(0.f, 0.f, 0.f, 0.f);
    } else if (b < 1076) {
        ((float4*)g_t)[(b - 826) * 256 + tid] = make_float4(0.f, 0.f, 0.f, 0.f);
    } else {
        for (int i = tid; i < NC; i += 256) g_counts[i] = 0.0f;
    }
}

// ---------------------------------------------------------------
// K2: fused symmetric gram + (argmax -> class scatter).
//  b in [0,640):       gram upper-tri 64x64 tiles, K-chunk 64 (10 tiles x 64
//                      K-splits), mirrored atomics for off-diagonal tiles.
//  b in [640,640+512): warp-per-row argmax of logits (8 rows/block, no bar),
//                      then scatter-add row into g_s (invn-weighted) / g_t.
// ---------------------------------------------------------------
__global__ void k_fused(const float* __restrict__ x,
                        const float* __restrict__ lg) {
    __shared__ float smem[2048];
    int b = blockIdx.x;
    int tid = threadIdx.x;

    if (b < 640) {
        const int ti_lut[10] = {0,0,0,0,1,1,1,2,2,3};
        const int tj_lut[10] = {0,1,2,3,1,2,3,2,3,3};
        float* As = smem;            // [16][64] : Xn[k][i-tile] (invn applied)
        float* Bs = smem + 1024;     // [16][64] : X [k][j-tile]
        int tile = b >> 6;           // 0..9
        int k0 = (b & 63) * 64;      // 64 K-splits of depth 64
        int i0 = ti_lut[tile] * 64, j0 = tj_lut[tile] * 64;
        int tx = tid & 15, ty = tid >> 4;

        float acc[4][4] = {};
#pragma unroll
        for (int kc = 0; kc < 64; kc += 16) {
#pragma unroll
            for (int l = 0; l < 4; l++) {
                int idx = tid + l * 256;          // 0..1023
                int kl = idx >> 6, col = idx & 63;
                int k = k0 + kc + kl;
                float inv = g_invn[k];
                As[kl * 64 + col] = x[(size_t)k * CH + i0 + col] * inv;
                Bs[kl * 64 + col] = x[(size_t)k * CH + j0 + col];
            }
            __syncthreads();
#pragma unroll
            for (int kl = 0; kl < 16; kl++) {
                float a[4], bb[4];
#pragma unroll
                for (int u = 0; u < 4; u++) a[u]  = As[kl * 64 + ty * 4 + u];
#pragma unroll
                for (int v = 0; v < 4; v++) bb[v] = Bs[kl * 64 + tx * 4 + v];
#pragma unroll
                for (int u = 0; u < 4; u++)
#pragma unroll
                    for (int v = 0; v < 4; v++)
                        acc[u][v] += a[u] * bb[v];
            }
            __syncthreads();
        }
        bool offdiag = (i0 != j0);
#pragma unroll
        for (int u = 0; u < 4; u++) {
            int i = i0 + ty * 4 + u;
#pragma unroll
            for (int v = 0; v < 4; v++) {
                int j = j0 + tx * 4 + v;
                atomicAdd(&g_G[i * CH + j], acc[u][v]);
                if (offdiag) atomicAdd(&g_G[j * CH + i], acc[u][v]);
            }
        }
    } else {
        // ---- warp-per-row argmax + scatter, 8 rows per block ----
        int row = ((b - 640) << 3) + (tid >> 5);
        int lane = tid & 31;
        const float4* p = (const float4*)(lg + (size_t)row * NC);  // 250 float4
        float best = -3.4e38f;
        int   bi = 0;
#pragma unroll
        for (int i = 0; i < 8; i++) {
            int idx = lane + (i << 5);
            if (idx < 250) {
                float4 v = p[idx];
                int c = idx << 2;
                if (v.x > best) { best = v.x; bi = c; }
                if (v.y > best) { best = v.y; bi = c + 1; }
                if (v.z > best) { best = v.z; bi = c + 2; }
                if (v.w > best) { best = v.w; bi = c + 3; }
            }
        }
#pragma unroll
        for (int off = 16; off; off >>= 1) {
            float ov = __shfl_xor_sync(0xffffffffu, best, off);
            int   oi = __shfl_xor_sync(0xffffffffu, bi,   off);
            if (ov > best || (ov == best && oi < bi)) { best = ov; bi = oi; }
        }
        int cls = bi;
        float inv = g_invn[row];
        const float4* px = (const float4*)(x + (size_t)row * CH);
#pragma unroll
        for (int j = 0; j < 2; j++) {
            int idx4 = lane + (j << 5);           // 0..63
            float4 xv = px[idx4];
            int base = cls * CH + (idx4 << 2);
            atomicAdd(&g_s[base + 0], xv.x * inv);
            atomicAdd(&g_s[base + 1], xv.y * inv);
            atomicAdd(&g_s[base + 2], xv.z * inv);
            atomicAdd(&g_s[base + 3], xv.w * inv);
            atomicAdd(&g_t[base + 0], xv.x);
            atomicAdd(&g_t[base + 1], xv.y);
            atomicAdd(&g_t[base + 2], xv.z);
            atomicAdd(&g_t[base + 3], xv.w);
        }
        if (lane == 0) atomicAdd(&g_counts[cls], 1.0f);
    }
}

// ---------------------------------------------------------------
// K3: prototypes: proto_c = (s_c @ G + t_c) / count  (0 if count==0)
// 63 blocks x 16 classes, 256 threads (thread = output column)
// ---------------------------------------------------------------
__global__ void k_proto(float* __restrict__ proto) {
    __shared__ float s_sm[16 * 256];
    int c0 = blockIdx.x * 16;
    int tid = threadIdx.x;

#pragma unroll
    for (int l = 0; l < 16; l++) {
        int cls = c0 + l;
        s_sm[l * 256 + tid] = (cls < NC) ? g_s[(size_t)cls * CH + tid] : 0.0f;
    }
    __syncthreads();

    float acc[16] = {};
#pragma unroll 4
    for (int k = 0; k < 256; k++) {
        float gk = g_G[k * CH + tid];
#pragma unroll
        for (int c = 0; c < 16; c++)
            acc[c] += s_sm[c * 256 + k] * gk;
    }
#pragma unroll
    for (int c = 0; c < 16; c++) {
        int cls = c0 + c;
        if (cls >= NC) break;
        float cnt = g_counts[cls];
        float v = 0.0f;
        if (cnt > 0.0f)
            v = (acc[c] + g_t[(size_t)cls * CH + tid]) / cnt;
        proto[(size_t)cls * CH + tid] = v;
    }
}

// ---------------------------------------------------------------
// K4: inter[i][j][:] = proto[j] - proto[i]   (1.02 GB, write-bound)
// 16x16 (i,j) tiles, smem-cached proto rows, float4 streaming stores.
// Interior blocks (62x62 of 63x63) take a check-free fast path.
// ---------------------------------------------------------------
__global__ void k_inter(const float* __restrict__ proto, float* __restrict__ inter) {
    __shared__ float4 pi[16][64];
    __shared__ float4 pj[16][64];
    int i0 = blockIdx.y * 16, j0 = blockIdx.x * 16;
    int tid = threadIdx.x;               // 256 threads

    const float4* p4 = (const float4*)proto;
#pragma unroll
    for (int l = 0; l < 4; l++) {
        int idx = tid + l * 256;         // 0..1023
        int r = idx >> 6, d = idx & 63;
        int gi = i0 + r, gj = j0 + r;
        pi[r][d] = (gi < NC) ? p4[gi * 64 + d] : make_float4(0.f, 0.f, 0.f, 0.f);
        pj[r][d] = (gj < NC) ? p4[gj * 64 + d] : make_float4(0.f, 0.f, 0.f, 0.f);
    }
    __syncthreads();

    int d = tid & 63;
    int p0 = tid >> 6;                   // 0..3
    float4* o4 = (float4*)inter;

    if (i0 + 16 <= NC && j0 + 16 <= NC) {
#pragma unroll 8
        for (int p = p0; p < 256; p += 4) {
            int il = p >> 4, jl = p & 15;
            float4 a = pj[jl][d];
            float4 bv = pi[il][d];
            float4 v = make_float4(a.x - bv.x, a.y - bv.y, a.z - bv.z, a.w - bv.w);
            __stcs(&o4[((size_t)(i0 + il) * NC + (j0 + jl)) * 64 + d], v);
        }
    } else {
        for (int p = p0; p < 256; p += 4) {
            int il = p >> 4, jl = p & 15;
            int i = i0 + il, j = j0 + jl;
            if (i < NC && j < NC) {
                float4 a = pj[jl][d];
                float4 bv = pi[il][d];
                float4 v = make_float4(a.x - bv.x, a.y - bv.y, a.z - bv.z, a.w - bv.w);
                __stcs(&o4[((size_t)i * NC + j) * 64 + d], v);
            }
        }
    }
}

// ---------------------------------------------------------------
extern "C" void kernel_launch(void* const* d_in, const int* in_sizes, int n_in,
                              void* d_out, int out_size) {
    const float* x  = (const float*)d_in[0];   // [4096, 256]
    const float* lg = (const float*)d_in[1];   // [4096, 1000]
    float* out   = (float*)d_out;
    float* proto = out;                         // [1000, 256]
    float* inter = out + (size_t)NC * CH;       // [1000, 1000, 256]

    k_prep <<<1077, 256>>>(x);
    k_fused<<<640 + 512, 256>>>(x, lg);
    k_proto<<<63, 256>>>(proto);
    k_inter<<<dim3(63, 63), 256>>>(proto, inter);
}

// round 5
// speedup vs baseline: 1.0059x; 1.0059x over previous
#include <cuda_runtime.h>
#include <cstddef>

#define N_ROWS 4096
#define CH     256
#define NC     1000
#define NTILE  10      // upper-triangle 64x64 tiles of 256x256
#define NSPLIT 64      // K-splits of depth 64 over K=4096

// ---- scratch (static device globals; no runtime allocation) ----
__device__ float g_invn[N_ROWS];
__device__ float g_G[CH * CH];                     // full (mirrored) gram
__device__ float g_part[NTILE * NSPLIT * 64 * 64]; // 10.5 MB partial tiles
__device__ float g_s[NC * CH];                     // per-class sum invn_r * x_r
__device__ float g_t[NC * CH];                     // per-class sum x_r
__device__ float g_counts[NC];

__constant__ int c_ti[NTILE] = {0,0,0,0,1,1,1,2,2,3};
__constant__ int c_tj[NTILE] = {0,1,2,3,1,2,3,2,3,3};

// ---------------------------------------------------------------
// K1: prep — norms + zero class accumulators (G not zeroed: fully
// overwritten by k_redG; g_part fully overwritten by k_fused).
//  b in [0,512)    : per-row inv-norms (warp/row, float4)
//  b in [512,762)  : zero g_s
//  b in [762,1012) : zero g_t
//  b == 1012       : zero g_counts
// ---------------------------------------------------------------
__global__ void k_prep(const float* __restrict__ x) {
    int b = blockIdx.x;
    int tid = threadIdx.x;
    if (b < 512) {
        int warp = ((b << 8) + tid) >> 5;       // 0..4095
        int lane = tid & 31;
        const float4* p = (const float4*)(x + (size_t)warp * CH);
        float ss = 0.0f;
#pragma unroll
        for (int k = lane; k < 64; k += 32) {
            float4 v = p[k];
            ss += v.x * v.x + v.y * v.y + v.z * v.z + v.w * v.w;
        }
#pragma unroll
        for (int off = 16; off; off >>= 1)
            ss += __shfl_xor_sync(0xffffffffu, ss, off);
        if (lane == 0) g_invn[warp] = rsqrtf(ss);
    } else if (b < 762) {
        ((float4*)g_s)[(b - 512) * 256 + tid] = make_float4(0.f, 0.f, 0.f, 0.f);
    } else if (b < 1012) {
        ((float4*)g_t)[(b - 762) * 256 + tid] = make_float4(0.f, 0.f, 0.f, 0.f);
    } else {
        for (int i = tid; i < NC; i += 256) g_counts[i] = 0.0f;
    }
}

// ---------------------------------------------------------------
// K2: fused gram-partials + (argmax -> class scatter).
//  b in [0,640):       gram upper-tri 64x64 tile, K-chunk 64; partial tile
//                      stored to g_part with plain float4 stores (no atomics).
//  b in [640,640+512): warp-per-row argmax of logits (8 rows/block),
//                      scatter-add row into g_s (invn-weighted) / g_t.
// ---------------------------------------------------------------
__global__ void k_fused(const float* __restrict__ x,
                        const float* __restrict__ lg) {
    __shared__ float smem[2048];
    int b = blockIdx.x;
    int tid = threadIdx.x;

    if (b < NTILE * NSPLIT) {
        float* As = smem;            // [16][64] : Xn[k][i-tile] (invn applied)
        float* Bs = smem + 1024;     // [16][64] : X [k][j-tile]
        int tile = b >> 6;           // 0..9
        int k0 = (b & 63) * 64;      // split * 64
        int i0 = c_ti[tile] * 64, j0 = c_tj[tile] * 64;
        int tx = tid & 15, ty = tid >> 4;

        float acc[4][4] = {};
#pragma unroll
        for (int kc = 0; kc < 64; kc += 16) {
#pragma unroll
            for (int l = 0; l < 4; l++) {
                int idx = tid + l * 256;          // 0..1023
                int kl = idx >> 6, col = idx & 63;
                int k = k0 + kc + kl;
                float inv = g_invn[k];
                As[kl * 64 + col] = x[(size_t)k * CH + i0 + col] * inv;
                Bs[kl * 64 + col] = x[(size_t)k * CH + j0 + col];
            }
            __syncthreads();
#pragma unroll
            for (int kl = 0; kl < 16; kl++) {
                float a[4], bb[4];
#pragma unroll
                for (int u = 0; u < 4; u++) a[u]  = As[kl * 64 + ty * 4 + u];
#pragma unroll
                for (int v = 0; v < 4; v++) bb[v] = Bs[kl * 64 + tx * 4 + v];
#pragma unroll
                for (int u = 0; u < 4; u++)
#pragma unroll
                    for (int v = 0; v < 4; v++)
                        acc[u][v] += a[u] * bb[v];
            }
            __syncthreads();
        }
        // store partial tile: coalesced float4 per (u-row)
        float4* p4 = (float4*)(g_part + (size_t)b * 4096);
#pragma unroll
        for (int u = 0; u < 4; u++)
            p4[(ty * 4 + u) * 16 + tx] =
                make_float4(acc[u][0], acc[u][1], acc[u][2], acc[u][3]);
    } else {
        // ---- warp-per-row argmax + scatter, 8 rows per block ----
        int row = ((b - NTILE * NSPLIT) << 3) + (tid >> 5);
        int lane = tid & 31;
        const float4* p = (const float4*)(lg + (size_t)row * NC);  // 250 float4
        float best = -3.4e38f;
        int   bi = 0;
#pragma unroll
        for (int i = 0; i < 8; i++) {
            int idx = lane + (i << 5);
            if (idx < 250) {
                float4 v = p[idx];
                int c = idx << 2;
                if (v.x > best) { best = v.x; bi = c; }
                if (v.y > best) { best = v.y; bi = c + 1; }
                if (v.z > best) { best = v.z; bi = c + 2; }
                if (v.w > best) { best = v.w; bi = c + 3; }
            }
        }
#pragma unroll
        for (int off = 16; off; off >>= 1) {
            float ov = __shfl_xor_sync(0xffffffffu, best, off);
            int   oi = __shfl_xor_sync(0xffffffffu, bi,   off);
            if (ov > best || (ov == best && oi < bi)) { best = ov; bi = oi; }
        }
        int cls = bi;
        float inv = g_invn[row];
        const float4* px = (const float4*)(x + (size_t)row * CH);
#pragma unroll
        for (int j = 0; j < 2; j++) {
            int idx4 = lane + (j << 5);           // 0..63
            float4 xv = px[idx4];
            int base = cls * CH + (idx4 << 2);
            atomicAdd(&g_s[base + 0], xv.x * inv);
            atomicAdd(&g_s[base + 1], xv.y * inv);
            atomicAdd(&g_s[base + 2], xv.z * inv);
            atomicAdd(&g_s[base + 3], xv.w * inv);
            atomicAdd(&g_t[base + 0], xv.x);
            atomicAdd(&g_t[base + 1], xv.y);
            atomicAdd(&g_t[base + 2], xv.z);
            atomicAdd(&g_t[base + 3], xv.w);
        }
        if (lane == 0) atomicAdd(&g_counts[cls], 1.0f);
    }
}

// ---------------------------------------------------------------
// K3: reduce partial gram tiles -> g_G, with symmetric mirror.
// 40 blocks x 256 threads; one float4 output element per thread.
// ---------------------------------------------------------------
__global__ void k_redG() {
    int idx = blockIdx.x * 256 + threadIdx.x;   // 0..10239
    int tile = idx >> 10;
    int p4   = idx & 1023;                      // float4 index in 64x64 tile
    int i0 = c_ti[tile] * 64, j0 = c_tj[tile] * 64;

    const float4* part4 = (const float4*)g_part;
    float4 sum = make_float4(0.f, 0.f, 0.f, 0.f);
#pragma unroll 8
    for (int s = 0; s < NSPLIT; s++) {
        float4 v = part4[(size_t)((tile << 6) + s) * 1024 + p4];
        sum.x += v.x; sum.y += v.y; sum.z += v.z; sum.w += v.w;
    }
    int il = p4 >> 4;              // 0..63
    int jb = (p4 & 15) << 2;       // 0,4,..,60
    int i = i0 + il, j = j0 + jb;
    ((float4*)g_G)[(i * CH + j) >> 2] = sum;
    if (i0 != j0) {
        g_G[(j + 0) * CH + i] = sum.x;
        g_G[(j + 1) * CH + i] = sum.y;
        g_G[(j + 2) * CH + i] = sum.z;
        g_G[(j + 3) * CH + i] = sum.w;
    }
}

// ---------------------------------------------------------------
// K4: prototypes: proto_c = (s_c @ G + t_c) / count  (0 if count==0)
// 63 blocks x 16 classes, 256 threads (thread = output column)
// ---------------------------------------------------------------
__global__ void k_proto(float* __restrict__ proto) {
    __shared__ float s_sm[16 * 256];
    int c0 = blockIdx.x * 16;
    int tid = threadIdx.x;

#pragma unroll
    for (int l = 0; l < 16; l++) {
        int cls = c0 + l;
        s_sm[l * 256 + tid] = (cls < NC) ? g_s[(size_t)cls * CH + tid] : 0.0f;
    }
    __syncthreads();

    float acc[16] = {};
#pragma unroll 4
    for (int k = 0; k < 256; k++) {
        float gk = g_G[k * CH + tid];
#pragma unroll
        for (int c = 0; c < 16; c++)
            acc[c] += s_sm[c * 256 + k] * gk;
    }
#pragma unroll
    for (int c = 0; c < 16; c++) {
        int cls = c0 + c;
        if (cls >= NC) break;
        float cnt = g_counts[cls];
        float v = 0.0f;
        if (cnt > 0.0f)
            v = (acc[c] + g_t[(size_t)cls * CH + tid]) / cnt;
        proto[(size_t)cls * CH + tid] = v;
    }
}

// ---------------------------------------------------------------
// K5: inter[i][j][:] = proto[j] - proto[i]   (1.02 GB, write-bound)
// 16x16 (i,j) tiles, smem-cached proto rows, float4 streaming stores.
// Interior blocks take a check-free fast path.
// ---------------------------------------------------------------
__global__ void k_inter(const float* __restrict__ proto, float* __restrict__ inter) {
    __shared__ float4 pi[16][64];
    __shared__ float4 pj[16][64];
    int i0 = blockIdx.y * 16, j0 = blockIdx.x * 16;
    int tid = threadIdx.x;               // 256 threads

    const float4* p4 = (const float4*)proto;
#pragma unroll
    for (int l = 0; l < 4; l++) {
        int idx = tid + l * 256;         // 0..1023
        int r = idx >> 6, d = idx & 63;
        int gi = i0 + r, gj = j0 + r;
        pi[r][d] = (gi < NC) ? p4[gi * 64 + d] : make_float4(0.f, 0.f, 0.f, 0.f);
        pj[r][d] = (gj < NC) ? p4[gj * 64 + d] : make_float4(0.f, 0.f, 0.f, 0.f);
    }
    __syncthreads();

    int d = tid & 63;
    int p0 = tid >> 6;                   // 0..3
    float4* o4 = (float4*)inter;

    if (i0 + 16 <= NC && j0 + 16 <= NC) {
#pragma unroll 8
        for (int p = p0; p < 256; p += 4) {
            int il = p >> 4, jl = p & 15;
            float4 a = pj[jl][d];
            float4 bv = pi[il][d];
            float4 v = make_float4(a.x - bv.x, a.y - bv.y, a.z - bv.z, a.w - bv.w);
            __stcs(&o4[((size_t)(i0 + il) * NC + (j0 + jl)) * 64 + d], v);
        }
    } else {
        for (int p = p0; p < 256; p += 4) {
            int il = p >> 4, jl = p & 15;
            int i = i0 + il, j = j0 + jl;
            if (i < NC && j < NC) {
                float4 a = pj[jl][d];
                float4 bv = pi[il][d];
                float4 v = make_float4(a.x - bv.x, a.y - bv.y, a.z - bv.z, a.w - bv.w);
                __stcs(&o4[((size_t)i * NC + j) * 64 + d], v);
            }
        }
    }
}

// ---------------------------------------------------------------
extern "C" void kernel_launch(void* const* d_in, const int* in_sizes, int n_in,
                              void* d_out, int out_size) {
    const float* x  = (const float*)d_in[0];   // [4096, 256]
    const float* lg = (const float*)d_in[1];   // [4096, 1000]
    float* out   = (float*)d_out;
    float* proto = out;                         // [1000, 256]
    float* inter = out + (size_t)NC * CH;       // [1000, 1000, 256]

    k_prep <<<1013, 256>>>(x);
    k_fused<<<NTILE * NSPLIT + 512, 256>>>(x, lg);
    k_redG <<<40, 256>>>();
    k_proto<<<63, 256>>>(proto);
    k_inter<<<dim3(63, 63), 256>>>(proto, inter);
}

// round 6
// speedup vs baseline: 1.0141x; 1.0082x over previous
#include <cuda_runtime.h>
#include <cstddef>

#define N_ROWS 4096
#define CH     256
#define NC     1000
#define NTILE  10      // upper-triangle 64x64 tiles of 256x256
#define NSPLIT 64      // K-splits of depth 64 over K=4096

// ---- scratch (static device globals; no runtime allocation) ----
__device__ float g_invn[N_ROWS];
__device__ float g_G[CH * CH];                     // full (mirrored) gram
__device__ float g_part[NTILE * NSPLIT * 64 * 64]; // 10.5 MB partial tiles
__device__ float g_s[NC * CH];                     // per-class sum invn_r * x_r
__device__ float g_t[NC * CH];                     // per-class sum x_r
__device__ float g_counts[NC];

__constant__ int c_ti[NTILE] = {0,0,0,0,1,1,1,2,2,3};
__constant__ int c_tj[NTILE] = {0,1,2,3,1,2,3,2,3,3};

// ---------------------------------------------------------------
// K1: prep — norms + zero class accumulators
// ---------------------------------------------------------------
__global__ void k_prep(const float* __restrict__ x) {
    int b = blockIdx.x;
    int tid = threadIdx.x;
    if (b < 512) {
        int warp = ((b << 8) + tid) >> 5;       // 0..4095
        int lane = tid & 31;
        const float4* p = (const float4*)(x + (size_t)warp * CH);
        float ss = 0.0f;
#pragma unroll
        for (int k = lane; k < 64; k += 32) {
            float4 v = p[k];
            ss += v.x * v.x + v.y * v.y + v.z * v.z + v.w * v.w;
        }
#pragma unroll
        for (int off = 16; off; off >>= 1)
            ss += __shfl_xor_sync(0xffffffffu, ss, off);
        if (lane == 0) g_invn[warp] = rsqrtf(ss);
    } else if (b < 762) {
        ((float4*)g_s)[(b - 512) * 256 + tid] = make_float4(0.f, 0.f, 0.f, 0.f);
    } else if (b < 1012) {
        ((float4*)g_t)[(b - 762) * 256 + tid] = make_float4(0.f, 0.f, 0.f, 0.f);
    } else {
        for (int i = tid; i < NC; i += 256) g_counts[i] = 0.0f;
    }
}

// ---------------------------------------------------------------
// K2: fused gram-partials + (argmax -> class scatter).
// ---------------------------------------------------------------
__global__ void k_fused(const float* __restrict__ x,
                        const float* __restrict__ lg) {
    __shared__ float smem[2048];
    int b = blockIdx.x;
    int tid = threadIdx.x;

    if (b < NTILE * NSPLIT) {
        float* As = smem;            // [16][64] : Xn[k][i-tile] (invn applied)
        float* Bs = smem + 1024;     // [16][64] : X [k][j-tile]
        int tile = b >> 6;           // 0..9
        int k0 = (b & 63) * 64;      // split * 64
        int i0 = c_ti[tile] * 64, j0 = c_tj[tile] * 64;
        int tx = tid & 15, ty = tid >> 4;

        float acc[4][4] = {};
#pragma unroll
        for (int kc = 0; kc < 64; kc += 16) {
#pragma unroll
            for (int l = 0; l < 4; l++) {
                int idx = tid + l * 256;          // 0..1023
                int kl = idx >> 6, col = idx & 63;
                int k = k0 + kc + kl;
                float inv = g_invn[k];
                As[kl * 64 + col] = x[(size_t)k * CH + i0 + col] * inv;
                Bs[kl * 64 + col] = x[(size_t)k * CH + j0 + col];
            }
            __syncthreads();
#pragma unroll
            for (int kl = 0; kl < 16; kl++) {
                float a[4], bb[4];
#pragma unroll
                for (int u = 0; u < 4; u++) a[u]  = As[kl * 64 + ty * 4 + u];
#pragma unroll
                for (int v = 0; v < 4; v++) bb[v] = Bs[kl * 64 + tx * 4 + v];
#pragma unroll
                for (int u = 0; u < 4; u++)
#pragma unroll
                    for (int v = 0; v < 4; v++)
                        acc[u][v] += a[u] * bb[v];
            }
            __syncthreads();
        }
        // store partial tile: coalesced float4 per (u-row)
        float4* p4 = (float4*)(g_part + (size_t)b * 4096);
#pragma unroll
        for (int u = 0; u < 4; u++)
            p4[(ty * 4 + u) * 16 + tx] =
                make_float4(acc[u][0], acc[u][1], acc[u][2], acc[u][3]);
    } else {
        // ---- warp-per-row argmax + scatter, 8 rows per block ----
        int row = ((b - NTILE * NSPLIT) << 3) + (tid >> 5);
        int lane = tid & 31;
        const float4* p = (const float4*)(lg + (size_t)row * NC);  // 250 float4
        float best = -3.4e38f;
        int   bi = 0;
#pragma unroll
        for (int i = 0; i < 8; i++) {
            int idx = lane + (i << 5);
            if (idx < 250) {
                float4 v = p[idx];
                int c = idx << 2;
                if (v.x > best) { best = v.x; bi = c; }
                if (v.y > best) { best = v.y; bi = c + 1; }
                if (v.z > best) { best = v.z; bi = c + 2; }
                if (v.w > best) { best = v.w; bi = c + 3; }
            }
        }
#pragma unroll
        for (int off = 16; off; off >>= 1) {
            float ov = __shfl_xor_sync(0xffffffffu, best, off);
            int   oi = __shfl_xor_sync(0xffffffffu, bi,   off);
            if (ov > best || (ov == best && oi < bi)) { best = ov; bi = oi; }
        }
        int cls = bi;
        float inv = g_invn[row];
        const float4* px = (const float4*)(x + (size_t)row * CH);
#pragma unroll
        for (int j = 0; j < 2; j++) {
            int idx4 = lane + (j << 5);           // 0..63
            float4 xv = px[idx4];
            int base = cls * CH + (idx4 << 2);
            atomicAdd(&g_s[base + 0], xv.x * inv);
            atomicAdd(&g_s[base + 1], xv.y * inv);
            atomicAdd(&g_s[base + 2], xv.z * inv);
            atomicAdd(&g_s[base + 3], xv.w * inv);
            atomicAdd(&g_t[base + 0], xv.x);
            atomicAdd(&g_t[base + 1], xv.y);
            atomicAdd(&g_t[base + 2], xv.z);
            atomicAdd(&g_t[base + 3], xv.w);
        }
        if (lane == 0) atomicAdd(&g_counts[cls], 1.0f);
    }
}

// ---------------------------------------------------------------
// K3: reduce partial gram tiles -> g_G, with symmetric mirror.
// ---------------------------------------------------------------
__global__ void k_redG() {
    int idx = blockIdx.x * 256 + threadIdx.x;   // 0..10239
    int tile = idx >> 10;
    int p4   = idx & 1023;                      // float4 index in 64x64 tile
    int i0 = c_ti[tile] * 64, j0 = c_tj[tile] * 64;

    const float4* part4 = (const float4*)g_part;
    float4 sum = make_float4(0.f, 0.f, 0.f, 0.f);
#pragma unroll 8
    for (int s = 0; s < NSPLIT; s++) {
        float4 v = part4[(size_t)((tile << 6) + s) * 1024 + p4];
        sum.x += v.x; sum.y += v.y; sum.z += v.z; sum.w += v.w;
    }
    int il = p4 >> 4;              // 0..63
    int jb = (p4 & 15) << 2;       // 0,4,..,60
    int i = i0 + il, j = j0 + jb;
    ((float4*)g_G)[(i * CH + j) >> 2] = sum;
    if (i0 != j0) {
        g_G[(j + 0) * CH + i] = sum.x;
        g_G[(j + 1) * CH + i] = sum.y;
        g_G[(j + 2) * CH + i] = sum.z;
        g_G[(j + 3) * CH + i] = sum.w;
    }
}

// ---------------------------------------------------------------
// K4: prototypes: proto_c = (s_c @ G + t_c) / count  (0 if count==0)
// 250 blocks x 4 classes; thread = (class cgrp, float4 column col4).
// One float4 G load + 4 FMA per k-iter, unroll 8 -> MLP 8.
// ---------------------------------------------------------------
__global__ void k_proto(float* __restrict__ proto) {
    __shared__ float s_sm[4 * 256];
    int c0 = blockIdx.x * 4;
    int tid = threadIdx.x;
    int cgrp = tid >> 6;          // 0..3  (class within block)
    int col4 = tid & 63;          // float4 column group

    // cooperative load of 4 s-rows (4*256 floats)
    {
        int c = tid >> 8;  // always 0 here; load via strided loop instead
        (void)c;
    }
#pragma unroll
    for (int l = 0; l < 4; l++) {
        int idx = tid + l * 256;          // 0..1023
        s_sm[idx] = g_s[(size_t)c0 * CH + idx];   // rows c0..c0+3 contiguous
    }
    __syncthreads();

    const float4* G4 = (const float4*)g_G;
    const float*  sr = s_sm + cgrp * 256;
    float4 acc = make_float4(0.f, 0.f, 0.f, 0.f);
#pragma unroll 8
    for (int k = 0; k < 256; k++) {
        float4 gv = G4[k * 64 + col4];
        float  sv = sr[k];
        acc.x += sv * gv.x;
        acc.y += sv * gv.y;
        acc.z += sv * gv.z;
        acc.w += sv * gv.w;
    }

    int cls = c0 + cgrp;
    float cnt = g_counts[cls];
    float4 tv = ((const float4*)g_t)[(size_t)cls * 64 + col4];
    float4 v = make_float4(0.f, 0.f, 0.f, 0.f);
    if (cnt > 0.0f) {
        float rc = 1.0f / cnt;
        v = make_float4((acc.x + tv.x) * rc, (acc.y + tv.y) * rc,
                        (acc.z + tv.z) * rc, (acc.w + tv.w) * rc);
    }
    ((float4*)proto)[(size_t)cls * 64 + col4] = v;
}

// ---------------------------------------------------------------
// K5: inter[i][j][:] = proto[j] - proto[i]   (1.02 GB, write-bound)
// ---------------------------------------------------------------
__global__ void k_inter(const float* __restrict__ proto, float* __restrict__ inter) {
    __shared__ float4 pi[16][64];
    __shared__ float4 pj[16][64];
    int i0 = blockIdx.y * 16, j0 = blockIdx.x * 16;
    int tid = threadIdx.x;               // 256 threads

    const float4* p4 = (const float4*)proto;
#pragma unroll
    for (int l = 0; l < 4; l++) {
        int idx = tid + l * 256;         // 0..1023
        int r = idx >> 6, d = idx & 63;
        int gi = i0 + r, gj = j0 + r;
        pi[r][d] = (gi < NC) ? p4[gi * 64 + d] : make_float4(0.f, 0.f, 0.f, 0.f);
        pj[r][d] = (gj < NC) ? p4[gj * 64 + d] : make_float4(0.f, 0.f, 0.f, 0.f);
    }
    __syncthreads();

    int d = tid & 63;
    int p0 = tid >> 6;                   // 0..3
    float4* o4 = (float4*)inter;

    if (i0 + 16 <= NC && j0 + 16 <= NC) {
#pragma unroll 8
        for (int p = p0; p < 256; p += 4) {
            int il = p >> 4, jl = p & 15;
            float4 a = pj[jl][d];
            float4 bv = pi[il][d];
            float4 v = make_float4(a.x - bv.x, a.y - bv.y, a.z - bv.z, a.w - bv.w);
            __stcs(&o4[((size_t)(i0 + il) * NC + (j0 + jl)) * 64 + d], v);
        }
    } else {
        for (int p = p0; p < 256; p += 4) {
            int il = p >> 4, jl = p & 15;
            int i = i0 + il, j = j0 + jl;
            if (i < NC && j < NC) {
                float4 a = pj[jl][d];
                float4 bv = pi[il][d];
                float4 v = make_float4(a.x - bv.x, a.y - bv.y, a.z - bv.z, a.w - bv.w);
                __stcs(&o4[((size_t)i * NC + j) * 64 + d], v);
            }
        }
    }
}

// ---------------------------------------------------------------
extern "C" void kernel_launch(void* const* d_in, const int* in_sizes, int n_in,
                              void* d_out, int out_size) {
    const float* x  = (const float*)d_in[0];   // [4096, 256]
    const float* lg = (const float*)d_in[1];   // [4096, 1000]
    float* out   = (float*)d_out;
    float* proto = out;                         // [1000, 256]
    float* inter = out + (size_t)NC * CH;       // [1000, 1000, 256]

    k_prep <<<1013, 256>>>(x);
    k_fused<<<NTILE * NSPLIT + 512, 256>>>(x, lg);
    k_redG <<<40, 256>>>();
    k_proto<<<250, 256>>>(proto);
    k_inter<<<dim3(63, 63), 256>>>(proto, inter);
}